// round 3
// baseline (speedup 1.0000x reference)
#include <cuda_runtime.h>
#include <math.h>

#define HID    1024
#define H3     3072
#define SEQ    512
#define VOCAB  32000
#define RGRID  128
#define RTHREADS 256

// ---------------- device scratch (static: no allocations allowed) ----------------
__device__ float g_X[2][SEQ][HID];                 // embedded enc/dec inputs
__device__ float g_GX[2][SEQ][H3];                 // precomputed Wih@x + bih
__device__ float g_dec_hs[SEQ][HID];               // decoder hidden states
__device__ unsigned long long g_ring[3][HID];      // (tag<<32)|float bits, depth-3 ring

// ---------------- packed f32x2 helpers (FFMA2) -----------------------------------
__device__ __forceinline__ unsigned long long pk2(float x, float y) {
    unsigned long long r;
    asm("mov.b64 %0,{%1,%2};" : "=l"(r) : "f"(x), "f"(y));
    return r;
}
__device__ __forceinline__ unsigned long long f2fma(unsigned long long a,
                                                    unsigned long long b,
                                                    unsigned long long c) {
    unsigned long long d;
    asm("fma.rn.f32x2 %0,%1,%2,%3;" : "=l"(d) : "l"(a), "l"(b), "l"(c));
    return d;
}
__device__ __forceinline__ float2 up2(unsigned long long v) {
    float2 f;
    asm("mov.b64 {%0,%1},%2;" : "=f"(f.x), "=f"(f.y) : "l"(v));
    return f;
}
__device__ __forceinline__ unsigned long long ldrx(const unsigned long long* p) {
    unsigned long long v;
    asm volatile("ld.global.relaxed.gpu.b64 %0,[%1];" : "=l"(v) : "l"(p));
    return v;
}
__device__ __forceinline__ void strx(unsigned long long* p, unsigned long long v) {
    asm volatile("st.global.relaxed.gpu.b64 [%0],%1;" :: "l"(p), "l"(v) : "memory");
}
__device__ __forceinline__ unsigned tf32r(float x) {
    unsigned u;
    asm("cvt.rna.tf32.f32 %0,%1;" : "=r"(u) : "f"(x));
    return u;
}

// ---------------- init: must reset per replay (graph re-executes) ----------------
__global__ void init_kernel() {
    int tid = threadIdx.x;                       // 1024 threads
    g_ring[0][tid] = 0ULL;                       // tag 0, value 0.0f
    g_ring[1][tid] = 0xFFFFFFFF00000000ULL;      // sentinel tag
    g_ring[2][tid] = 0xFFFFFFFF00000000ULL;
}

// ---------------- embedding gather (encoder + teacher-forced decoder) ------------
__global__ void gather_kernel(const int* __restrict__ inputs,
                              const int* __restrict__ targets,
                              const float* __restrict__ emb) {
    int b = blockIdx.x;
    int phase = b >> 9;
    int t = b & (SEQ - 1);
    int tok = phase ? (t == 0 ? 0 : targets[t - 1]) : inputs[t];
    const float4* src = (const float4*)(emb + (size_t)tok * HID);
    float4* dst = (float4*)(&g_X[phase][t][0]);
    dst[threadIdx.x] = src[threadIdx.x];
}

// ---------------- fp32 NT GEMM (FFMA2) for the two gx precomputes ----------------
// grid.z = phase.  C = g_GX[z] = g_X[z] * Wih[z]^T + bih[z], N = 3072, K = 1024.
__global__ void __launch_bounds__(256, 2) gemm_gx_kernel(
    const float* __restrict__ B0, const float* __restrict__ B1,
    const float* __restrict__ bias0, const float* __restrict__ bias1)
{
    const int K = HID, N = H3;
    int mode = blockIdx.z;
    const float* A = &g_X[mode][0][0];
    const float* B = mode ? B1 : B0;
    const float* bias = mode ? bias1 : bias0;
    float* C = &g_GX[mode][0][0];

    __shared__ float As[2][16][132];
    __shared__ float Bs[2][16][132];

    int tid = threadIdx.x;
    int bm = blockIdx.y * 128;
    int bn = blockIdx.x * 128;
    int lrow = tid >> 2;
    int lcol = (tid & 3) << 2;
    int tx = tid & 15;
    int ty = tid >> 4;
    const float* Ab = A + (size_t)bm * K;
    const float* Bb = B + (size_t)bn * K;

    unsigned long long acc2[8][4];
#pragma unroll
    for (int i = 0; i < 8; ++i)
#pragma unroll
        for (int j = 0; j < 4; ++j) acc2[i][j] = 0ULL;

    float4 pa[2], pb[2];
#pragma unroll
    for (int r = 0; r < 2; ++r) {
        int row = lrow + r * 64;
        pa[r] = *(const float4*)(Ab + (size_t)row * K + lcol);
        pb[r] = *(const float4*)(Bb + (size_t)row * K + lcol);
    }
#pragma unroll
    for (int r = 0; r < 2; ++r) {
        int row = lrow + r * 64;
        As[0][lcol + 0][row] = pa[r].x; As[0][lcol + 1][row] = pa[r].y;
        As[0][lcol + 2][row] = pa[r].z; As[0][lcol + 3][row] = pa[r].w;
        Bs[0][lcol + 0][row] = pb[r].x; Bs[0][lcol + 1][row] = pb[r].y;
        Bs[0][lcol + 2][row] = pb[r].z; Bs[0][lcol + 3][row] = pb[r].w;
    }
    __syncthreads();

    int cur = 0;
    for (int k0 = 0; k0 < K; k0 += 16) {
        bool more = (k0 + 16) < K;
        if (more) {
#pragma unroll
            for (int r = 0; r < 2; ++r) {
                int row = lrow + r * 64;
                pa[r] = *(const float4*)(Ab + (size_t)row * K + k0 + 16 + lcol);
                pb[r] = *(const float4*)(Bb + (size_t)row * K + k0 + 16 + lcol);
            }
        }
#pragma unroll
        for (int kk = 0; kk < 16; ++kk) {
            float4 av0 = *(const float4*)&As[cur][kk][ty * 8];
            float4 av1 = *(const float4*)&As[cur][kk][ty * 8 + 4];
            ulonglong2 bv0 = *(const ulonglong2*)&Bs[cur][kk][tx * 8];
            ulonglong2 bv1 = *(const ulonglong2*)&Bs[cur][kk][tx * 8 + 4];
            unsigned long long a2[8];
            a2[0] = pk2(av0.x, av0.x); a2[1] = pk2(av0.y, av0.y);
            a2[2] = pk2(av0.z, av0.z); a2[3] = pk2(av0.w, av0.w);
            a2[4] = pk2(av1.x, av1.x); a2[5] = pk2(av1.y, av1.y);
            a2[6] = pk2(av1.z, av1.z); a2[7] = pk2(av1.w, av1.w);
#pragma unroll
            for (int i = 0; i < 8; ++i) {
                acc2[i][0] = f2fma(a2[i], bv0.x, acc2[i][0]);
                acc2[i][1] = f2fma(a2[i], bv0.y, acc2[i][1]);
                acc2[i][2] = f2fma(a2[i], bv1.x, acc2[i][2]);
                acc2[i][3] = f2fma(a2[i], bv1.y, acc2[i][3]);
            }
        }
        if (more) {
            int alt = cur ^ 1;
#pragma unroll
            for (int r = 0; r < 2; ++r) {
                int row = lrow + r * 64;
                As[alt][lcol + 0][row] = pa[r].x; As[alt][lcol + 1][row] = pa[r].y;
                As[alt][lcol + 2][row] = pa[r].z; As[alt][lcol + 3][row] = pa[r].w;
                Bs[alt][lcol + 0][row] = pb[r].x; Bs[alt][lcol + 1][row] = pb[r].y;
                Bs[alt][lcol + 2][row] = pb[r].z; Bs[alt][lcol + 3][row] = pb[r].w;
            }
        }
        __syncthreads();
        cur ^= 1;
    }

#pragma unroll
    for (int i = 0; i < 8; ++i) {
        int row = bm + ty * 8 + i;
        float2 c0 = up2(acc2[i][0]), c1 = up2(acc2[i][1]);
        float2 c2 = up2(acc2[i][2]), c3 = up2(acc2[i][3]);
        int col = bn + tx * 8;
        float4 o0, o1;
        o0.x = c0.x + bias[col + 0]; o0.y = c0.y + bias[col + 1];
        o0.z = c1.x + bias[col + 2]; o0.w = c1.y + bias[col + 3];
        o1.x = c2.x + bias[col + 4]; o1.y = c2.y + bias[col + 5];
        o1.z = c3.x + bias[col + 6]; o1.w = c3.y + bias[col + 7];
        *(float4*)(C + (size_t)row * N + col) = o0;
        *(float4*)(C + (size_t)row * N + col + 4) = o1;
    }
}

// ---------------- tf32 tensor-core projection: out = dec_hs * proj_W^T + b -------
// Block 128x128, K-tile 32, 8 warps (2m x 4n), warp tile 64x32 via m16n8k8 tf32.
// smem rows padded to 36 floats -> bank index 4g+c, conflict-free fragment loads.
#define LDT 36
#define TBUF (128 * LDT)            // floats per A (or B) buffer
__global__ void __launch_bounds__(256, 1) proj_mma_kernel(
    const float* __restrict__ W, const float* __restrict__ bias,
    float* __restrict__ C)
{
    extern __shared__ float ps[];   // [2][A:TBUF | B:TBUF]
    const float* A = &g_dec_hs[0][0];

    int tid = threadIdx.x;
    int lane = tid & 31, wid = tid >> 5;
    int bm = blockIdx.y * 128, bn = blockIdx.x * 128;
    int warp_m = (wid & 1) * 64, warp_n = (wid >> 1) * 32;
    int g = lane >> 2, q = lane & 3;

    int lrow = tid >> 3;            // 0..31
    int lcol = (tid & 7) * 4;       // k within tile
    const float* Ag = A + (size_t)(bm + lrow) * HID + lcol;
    const float* Bg = W + (size_t)(bn + lrow) * HID + lcol;

    float c[4][4][4];
#pragma unroll
    for (int a = 0; a < 4; ++a)
#pragma unroll
        for (int b = 0; b < 4; ++b)
#pragma unroll
            for (int r = 0; r < 4; ++r) c[a][b][r] = 0.f;

    float4 ra[4], rb[4];
    // prologue: k-tile 0
#pragma unroll
    for (int r = 0; r < 4; ++r) {
        ra[r] = *(const float4*)(Ag + (size_t)r * 32 * HID);
        rb[r] = *(const float4*)(Bg + (size_t)r * 32 * HID);
    }
    {
        float* As = ps;
        float* Bs = ps + TBUF;
#pragma unroll
        for (int r = 0; r < 4; ++r) {
            int ro = (lrow + r * 32) * LDT + lcol;
            As[ro + 0] = __uint_as_float(tf32r(ra[r].x));
            As[ro + 1] = __uint_as_float(tf32r(ra[r].y));
            As[ro + 2] = __uint_as_float(tf32r(ra[r].z));
            As[ro + 3] = __uint_as_float(tf32r(ra[r].w));
            Bs[ro + 0] = __uint_as_float(tf32r(rb[r].x));
            Bs[ro + 1] = __uint_as_float(tf32r(rb[r].y));
            Bs[ro + 2] = __uint_as_float(tf32r(rb[r].z));
            Bs[ro + 3] = __uint_as_float(tf32r(rb[r].w));
        }
    }
    __syncthreads();

    for (int kt = 0; kt < HID / 32; ++kt) {
        bool more = kt + 1 < HID / 32;
        if (more) {
            const float* Ak = Ag + (kt + 1) * 32;
            const float* Bk = Bg + (kt + 1) * 32;
#pragma unroll
            for (int r = 0; r < 4; ++r) {
                ra[r] = *(const float4*)(Ak + (size_t)r * 32 * HID);
                rb[r] = *(const float4*)(Bk + (size_t)r * 32 * HID);
            }
        }
        const float* As = ps + (kt & 1) * 2 * TBUF;
        const float* Bs = As + TBUF;
#pragma unroll
        for (int kk = 0; kk < 4; ++kk) {
            unsigned af[4][4], bf[4][2];
#pragma unroll
            for (int fm = 0; fm < 4; ++fm) {
                int rb0 = (warp_m + fm * 16 + g) * LDT + kk * 8;
                af[fm][0] = __float_as_uint(As[rb0 + q]);
                af[fm][1] = __float_as_uint(As[rb0 + 8 * LDT + q]);
                af[fm][2] = __float_as_uint(As[rb0 + q + 4]);
                af[fm][3] = __float_as_uint(As[rb0 + 8 * LDT + q + 4]);
            }
#pragma unroll
            for (int fn = 0; fn < 4; ++fn) {
                int nb = (warp_n + fn * 8 + g) * LDT + kk * 8;
                bf[fn][0] = __float_as_uint(Bs[nb + q]);
                bf[fn][1] = __float_as_uint(Bs[nb + q + 4]);
            }
#pragma unroll
            for (int fm = 0; fm < 4; ++fm)
#pragma unroll
                for (int fn = 0; fn < 4; ++fn)
                    asm volatile(
                        "mma.sync.aligned.m16n8k8.row.col.f32.tf32.tf32.f32 "
                        "{%0,%1,%2,%3},{%4,%5,%6,%7},{%8,%9},{%0,%1,%2,%3};"
                        : "+f"(c[fm][fn][0]), "+f"(c[fm][fn][1]),
                          "+f"(c[fm][fn][2]), "+f"(c[fm][fn][3])
                        : "r"(af[fm][0]), "r"(af[fm][1]),
                          "r"(af[fm][2]), "r"(af[fm][3]),
                          "r"(bf[fn][0]), "r"(bf[fn][1]));
        }
        if (more) {
            float* Aw = ps + ((kt + 1) & 1) * 2 * TBUF;
            float* Bw = Aw + TBUF;
#pragma unroll
            for (int r = 0; r < 4; ++r) {
                int ro = (lrow + r * 32) * LDT + lcol;
                Aw[ro + 0] = __uint_as_float(tf32r(ra[r].x));
                Aw[ro + 1] = __uint_as_float(tf32r(ra[r].y));
                Aw[ro + 2] = __uint_as_float(tf32r(ra[r].z));
                Aw[ro + 3] = __uint_as_float(tf32r(ra[r].w));
                Bw[ro + 0] = __uint_as_float(tf32r(rb[r].x));
                Bw[ro + 1] = __uint_as_float(tf32r(rb[r].y));
                Bw[ro + 2] = __uint_as_float(tf32r(rb[r].z));
                Bw[ro + 3] = __uint_as_float(tf32r(rb[r].w));
            }
        }
        __syncthreads();
    }

    // epilogue: bias + store (float2 per fragment row)
#pragma unroll
    for (int fm = 0; fm < 4; ++fm) {
        int row0 = bm + warp_m + fm * 16 + g;
#pragma unroll
        for (int fn = 0; fn < 4; ++fn) {
            int col = bn + warp_n + fn * 8 + q * 2;
            float b0 = bias[col], b1 = bias[col + 1];
            float2 o0 = make_float2(c[fm][fn][0] + b0, c[fm][fn][1] + b1);
            float2 o1 = make_float2(c[fm][fn][2] + b0, c[fm][fn][3] + b1);
            *(float2*)(C + (size_t)row0 * VOCAB + col) = o0;
            *(float2*)(C + (size_t)(row0 + 8) * VOCAB + col) = o1;
        }
    }
}

// ---------------- persistent GRU recurrence, barrier-light ring ------------------
// 128 CTAs x 256 threads; warp w owns h index i = blk*8+w, Whh rows in registers.
// Each thread spins independently on its own 4 contiguous ring words (one 32B
// sector), stages into a double-buffered smem h; ONE __syncthreads per step.
__global__ void __launch_bounds__(RTHREADS, 1) recurrence_kernel(
    const float* __restrict__ enc_Whh, const float* __restrict__ enc_bhh,
    const float* __restrict__ dec_Whh, const float* __restrict__ dec_bhh)
{
    extern __shared__ float smem[];
    float* shbuf = smem;               // 2 x HID floats (double-buffered h)
    float* sgx   = smem + 2 * HID;     // SEQ*24 floats: this CTA's gx slice

    int tid = threadIdx.x;
    int warp = tid >> 5, lane = tid & 31;
    int base = blockIdx.x * 8;
    int i = base + warp;
    int s = 0;

    unsigned long long wr2[16], wz2[16], wn2[16];

    for (int phase = 0; phase < 2; ++phase) {
        const float* Whh = phase ? dec_Whh : enc_Whh;
        const float* bhh = phase ? dec_bhh : enc_bhh;
        const float* gxp = &g_GX[phase][0][0];

        {
            const float* w0 = Whh + (size_t)i * HID;
            const float* w1 = Whh + (size_t)(HID + i) * HID;
            const float* w2 = Whh + (size_t)(2 * HID + i) * HID;
#pragma unroll
            for (int k = 0; k < 8; ++k) {
                int cc = 4 * lane + 128 * k;
                float4 a = *(const float4*)(w0 + cc);
                wr2[2*k] = pk2(a.x, a.y); wr2[2*k+1] = pk2(a.z, a.w);
                float4 b = *(const float4*)(w1 + cc);
                wz2[2*k] = pk2(b.x, b.y); wz2[2*k+1] = pk2(b.z, b.w);
                float4 d = *(const float4*)(w2 + cc);
                wn2[2*k] = pk2(d.x, d.y); wn2[2*k+1] = pk2(d.z, d.w);
            }
        }
        float br = bhh[i], bz = bhh[HID + i], bnn = bhh[2 * HID + i];

        __syncthreads();               // all warps done with previous phase's sgx
        for (int idx = tid; idx < SEQ * 24; idx += RTHREADS) {
            int t = idx / 24;
            int rr = idx - t * 24;
            int w = rr / 3, gg = rr - 3 * w;
            sgx[idx] = gxp[(size_t)t * H3 + gg * HID + base + w];
        }
        __syncthreads();

        for (int t = 0; t < SEQ; ++t, ++s) {
            const unsigned long long* ring = g_ring[s % 3] + 4 * tid;
            unsigned exp = (unsigned)s;
            unsigned long long v0 = ldrx(ring);
            unsigned long long v1 = ldrx(ring + 1);
            unsigned long long v2 = ldrx(ring + 2);
            unsigned long long v3 = ldrx(ring + 3);
            while ((unsigned)(v0 >> 32) != exp) v0 = ldrx(ring);
            while ((unsigned)(v1 >> 32) != exp) v1 = ldrx(ring + 1);
            while ((unsigned)(v2 >> 32) != exp) v2 = ldrx(ring + 2);
            while ((unsigned)(v3 >> 32) != exp) v3 = ldrx(ring + 3);

            float* sh = shbuf + (s & 1) * HID;
            int e = 4 * tid;
            sh[e + 0] = __uint_as_float((unsigned)v0);
            sh[e + 1] = __uint_as_float((unsigned)v1);
            sh[e + 2] = __uint_as_float((unsigned)v2);
            sh[e + 3] = __uint_as_float((unsigned)v3);
            __syncthreads();           // the ONLY barrier in the step

            unsigned long long ar2 = 0ULL, az2 = 0ULL, an2 = 0ULL;
            const ulonglong2* shv = (const ulonglong2*)sh;
#pragma unroll
            for (int k = 0; k < 8; ++k) {
                ulonglong2 hv = shv[lane + 32 * k];
                ar2 = f2fma(wr2[2*k], hv.x, ar2); ar2 = f2fma(wr2[2*k+1], hv.y, ar2);
                az2 = f2fma(wz2[2*k], hv.x, az2); az2 = f2fma(wz2[2*k+1], hv.y, az2);
                an2 = f2fma(wn2[2*k], hv.x, an2); an2 = f2fma(wn2[2*k+1], hv.y, an2);
            }
            float2 arf = up2(ar2), azf = up2(az2), anf = up2(an2);
            float ar = arf.x + arf.y, az = azf.x + azf.y, an = anf.x + anf.y;
#pragma unroll
            for (int off = 16; off > 0; off >>= 1) {
                ar += __shfl_xor_sync(0xffffffffu, ar, off);
                az += __shfl_xor_sync(0xffffffffu, az, off);
                an += __shfl_xor_sync(0xffffffffu, an, off);
            }
            if (lane == 0) {
                const float* gx3 = &sgx[t * 24 + warp * 3];
                float r = 1.f / (1.f + expf(-(gx3[0] + ar + br)));
                float z = 1.f / (1.f + expf(-(gx3[1] + az + bz)));
                float n = tanhf(gx3[2] + r * (an + bnn));
                float hnew = (1.f - z) * n + z * sh[i];
                if (phase) g_dec_hs[t][i] = hnew;
                unsigned long long pub =
                    ((unsigned long long)(unsigned)(s + 1) << 32) |
                    (unsigned long long)__float_as_uint(hnew);
                strx(&g_ring[(s + 1) % 3][i], pub);
            }
            // no trailing barrier: sh is double-buffered, ring depth 3 covers skew
        }
    }
}

// ---------------- launch ----------------
extern "C" void kernel_launch(void* const* d_in, const int* in_sizes, int n_in,
                              void* d_out, int out_size) {
    const int*   inputs  = (const int*)d_in[0];
    const int*   targets = (const int*)d_in[1];
    const float* emb     = (const float*)d_in[2];
    const float* enc_Wih = (const float*)d_in[3];
    const float* enc_Whh = (const float*)d_in[4];
    const float* enc_bih = (const float*)d_in[5];
    const float* enc_bhh = (const float*)d_in[6];
    const float* dec_Wih = (const float*)d_in[7];
    const float* dec_Whh = (const float*)d_in[8];
    const float* dec_bih = (const float*)d_in[9];
    const float* dec_bhh = (const float*)d_in[10];
    const float* proj_W  = (const float*)d_in[11];
    const float* proj_b  = (const float*)d_in[12];
    float* out = (float*)d_out;

    const int rec_smem  = (2 * HID + SEQ * 24) * 4;      // 57,344 B
    const int proj_smem = 4 * TBUF * 4;                  // 73,728 B
    cudaFuncSetAttribute(recurrence_kernel,
                         cudaFuncAttributeMaxDynamicSharedMemorySize, rec_smem);
    cudaFuncSetAttribute(proj_mma_kernel,
                         cudaFuncAttributeMaxDynamicSharedMemorySize, proj_smem);

    init_kernel<<<1, 1024>>>();
    gather_kernel<<<2 * SEQ, 256>>>(inputs, targets, emb);

    dim3 g_gx(H3 / 128, SEQ / 128, 2);        // 24 x 4 x 2 = 192 blocks, one wave
    gemm_gx_kernel<<<g_gx, 256>>>(enc_Wih, dec_Wih, enc_bih, dec_bih);

    recurrence_kernel<<<RGRID, RTHREADS, rec_smem>>>(enc_Whh, enc_bhh,
                                                     dec_Whh, dec_bhh);

    dim3 g_proj(VOCAB / 128, SEQ / 128);      // 250 x 4
    proj_mma_kernel<<<g_proj, 256, proj_smem>>>(proj_W, proj_b, out);
}

// round 4
// speedup vs baseline: 1.5864x; 1.5864x over previous
#include <cuda_runtime.h>
#include <math.h>

#define HID    1024
#define H3     3072
#define SEQ    512
#define VOCAB  32000
#define RGRID  128
#define RTHREADS 256

// ---------------- device scratch (static: no allocations allowed) ----------------
__device__ float g_X[2][SEQ][HID];                 // embedded enc/dec inputs
__device__ float g_GX[2][SEQ][H3];                 // precomputed Wih@x + bih
__device__ float g_dec_hs[SEQ][HID];               // decoder hidden states
__device__ unsigned long long g_ring[3][HID];      // (tag<<32)|float bits, depth-3 ring

// ---------------- packed f32x2 helpers (FFMA2) -----------------------------------
__device__ __forceinline__ unsigned long long pk2(float x, float y) {
    unsigned long long r;
    asm("mov.b64 %0,{%1,%2};" : "=l"(r) : "f"(x), "f"(y));
    return r;
}
__device__ __forceinline__ unsigned long long f2fma(unsigned long long a,
                                                    unsigned long long b,
                                                    unsigned long long c) {
    unsigned long long d;
    asm("fma.rn.f32x2 %0,%1,%2,%3;" : "=l"(d) : "l"(a), "l"(b), "l"(c));
    return d;
}
__device__ __forceinline__ float2 up2(unsigned long long v) {
    float2 f;
    asm("mov.b64 {%0,%1},%2;" : "=f"(f.x), "=f"(f.y) : "l"(v));
    return f;
}
__device__ __forceinline__ unsigned long long ldrx(const unsigned long long* p) {
    unsigned long long v;
    asm volatile("ld.global.relaxed.gpu.b64 %0,[%1];" : "=l"(v) : "l"(p));
    return v;
}
__device__ __forceinline__ void strx(unsigned long long* p, unsigned long long v) {
    asm volatile("st.global.relaxed.gpu.b64 [%0],%1;" :: "l"(p), "l"(v) : "memory");
}
__device__ __forceinline__ unsigned tf32r(float x) {
    unsigned u;
    asm("cvt.rna.tf32.f32 %0,%1;" : "=r"(u) : "f"(x));
    return u;
}

// ---------------- init: must reset per replay (graph re-executes) ----------------
__global__ void init_kernel() {
    int tid = threadIdx.x;                       // 1024 threads
    g_ring[0][tid] = 0ULL;                       // tag 0, value 0.0f
    g_ring[1][tid] = 0xFFFFFFFF00000000ULL;      // sentinel tag
    g_ring[2][tid] = 0xFFFFFFFF00000000ULL;
}

// ---------------- embedding gather (encoder + teacher-forced decoder) ------------
__global__ void gather_kernel(const int* __restrict__ inputs,
                              const int* __restrict__ targets,
                              const float* __restrict__ emb) {
    int b = blockIdx.x;
    int phase = b >> 9;
    int t = b & (SEQ - 1);
    int tok = phase ? (t == 0 ? 0 : targets[t - 1]) : inputs[t];
    const float4* src = (const float4*)(emb + (size_t)tok * HID);
    float4* dst = (float4*)(&g_X[phase][t][0]);
    dst[threadIdx.x] = src[threadIdx.x];
}

// ---------------- fp32 NT GEMM (FFMA2) for the two gx precomputes ----------------
// grid.z = phase.  C = g_GX[z] = g_X[z] * Wih[z]^T + bih[z], N = 3072, K = 1024.
__global__ void __launch_bounds__(256, 2) gemm_gx_kernel(
    const float* __restrict__ B0, const float* __restrict__ B1,
    const float* __restrict__ bias0, const float* __restrict__ bias1)
{
    const int K = HID, N = H3;
    int mode = blockIdx.z;
    const float* A = &g_X[mode][0][0];
    const float* B = mode ? B1 : B0;
    const float* bias = mode ? bias1 : bias0;
    float* C = &g_GX[mode][0][0];

    __shared__ float As[2][16][132];
    __shared__ float Bs[2][16][132];

    int tid = threadIdx.x;
    int bm = blockIdx.y * 128;
    int bn = blockIdx.x * 128;
    int lrow = tid >> 2;
    int lcol = (tid & 3) << 2;
    int tx = tid & 15;
    int ty = tid >> 4;
    const float* Ab = A + (size_t)bm * K;
    const float* Bb = B + (size_t)bn * K;

    unsigned long long acc2[8][4];
#pragma unroll
    for (int i = 0; i < 8; ++i)
#pragma unroll
        for (int j = 0; j < 4; ++j) acc2[i][j] = 0ULL;

    float4 pa[2], pb[2];
#pragma unroll
    for (int r = 0; r < 2; ++r) {
        int row = lrow + r * 64;
        pa[r] = *(const float4*)(Ab + (size_t)row * K + lcol);
        pb[r] = *(const float4*)(Bb + (size_t)row * K + lcol);
    }
#pragma unroll
    for (int r = 0; r < 2; ++r) {
        int row = lrow + r * 64;
        As[0][lcol + 0][row] = pa[r].x; As[0][lcol + 1][row] = pa[r].y;
        As[0][lcol + 2][row] = pa[r].z; As[0][lcol + 3][row] = pa[r].w;
        Bs[0][lcol + 0][row] = pb[r].x; Bs[0][lcol + 1][row] = pb[r].y;
        Bs[0][lcol + 2][row] = pb[r].z; Bs[0][lcol + 3][row] = pb[r].w;
    }
    __syncthreads();

    int cur = 0;
    for (int k0 = 0; k0 < K; k0 += 16) {
        bool more = (k0 + 16) < K;
        if (more) {
#pragma unroll
            for (int r = 0; r < 2; ++r) {
                int row = lrow + r * 64;
                pa[r] = *(const float4*)(Ab + (size_t)row * K + k0 + 16 + lcol);
                pb[r] = *(const float4*)(Bb + (size_t)row * K + k0 + 16 + lcol);
            }
        }
#pragma unroll
        for (int kk = 0; kk < 16; ++kk) {
            float4 av0 = *(const float4*)&As[cur][kk][ty * 8];
            float4 av1 = *(const float4*)&As[cur][kk][ty * 8 + 4];
            ulonglong2 bv0 = *(const ulonglong2*)&Bs[cur][kk][tx * 8];
            ulonglong2 bv1 = *(const ulonglong2*)&Bs[cur][kk][tx * 8 + 4];
            unsigned long long a2[8];
            a2[0] = pk2(av0.x, av0.x); a2[1] = pk2(av0.y, av0.y);
            a2[2] = pk2(av0.z, av0.z); a2[3] = pk2(av0.w, av0.w);
            a2[4] = pk2(av1.x, av1.x); a2[5] = pk2(av1.y, av1.y);
            a2[6] = pk2(av1.z, av1.z); a2[7] = pk2(av1.w, av1.w);
#pragma unroll
            for (int i = 0; i < 8; ++i) {
                acc2[i][0] = f2fma(a2[i], bv0.x, acc2[i][0]);
                acc2[i][1] = f2fma(a2[i], bv0.y, acc2[i][1]);
                acc2[i][2] = f2fma(a2[i], bv1.x, acc2[i][2]);
                acc2[i][3] = f2fma(a2[i], bv1.y, acc2[i][3]);
            }
        }
        if (more) {
            int alt = cur ^ 1;
#pragma unroll
            for (int r = 0; r < 2; ++r) {
                int row = lrow + r * 64;
                As[alt][lcol + 0][row] = pa[r].x; As[alt][lcol + 1][row] = pa[r].y;
                As[alt][lcol + 2][row] = pa[r].z; As[alt][lcol + 3][row] = pa[r].w;
                Bs[alt][lcol + 0][row] = pb[r].x; Bs[alt][lcol + 1][row] = pb[r].y;
                Bs[alt][lcol + 2][row] = pb[r].z; Bs[alt][lcol + 3][row] = pb[r].w;
            }
        }
        __syncthreads();
        cur ^= 1;
    }

#pragma unroll
    for (int i = 0; i < 8; ++i) {
        int row = bm + ty * 8 + i;
        float2 c0 = up2(acc2[i][0]), c1 = up2(acc2[i][1]);
        float2 c2 = up2(acc2[i][2]), c3 = up2(acc2[i][3]);
        int col = bn + tx * 8;
        float4 o0, o1;
        o0.x = c0.x + bias[col + 0]; o0.y = c0.y + bias[col + 1];
        o0.z = c1.x + bias[col + 2]; o0.w = c1.y + bias[col + 3];
        o1.x = c2.x + bias[col + 4]; o1.y = c2.y + bias[col + 5];
        o1.z = c3.x + bias[col + 6]; o1.w = c3.y + bias[col + 7];
        *(float4*)(C + (size_t)row * N + col) = o0;
        *(float4*)(C + (size_t)row * N + col + 4) = o1;
    }
}

// ---------------- tf32 tensor-core projection: out = dec_hs * proj_W^T + b -------
// Block 128x128, K-tile 32, 8 warps (2m x 4n), warp tile 64x32 via m16n8k8 tf32.
#define LDT 36
#define TBUF (128 * LDT)            // floats per A (or B) buffer
__global__ void __launch_bounds__(256, 2) proj_mma_kernel(
    const float* __restrict__ W, const float* __restrict__ bias,
    float* __restrict__ C)
{
    extern __shared__ float ps[];   // [2][A:TBUF | B:TBUF]
    const float* A = &g_dec_hs[0][0];

    int tid = threadIdx.x;
    int lane = tid & 31, wid = tid >> 5;
    int bm = blockIdx.y * 128, bn = blockIdx.x * 128;
    int warp_m = (wid & 1) * 64, warp_n = (wid >> 1) * 32;
    int g = lane >> 2, q = lane & 3;

    int lrow = tid >> 3;            // 0..31
    int lcol = (tid & 7) * 4;       // k within tile
    const float* Ag = A + (size_t)(bm + lrow) * HID + lcol;
    const float* Bg = W + (size_t)(bn + lrow) * HID + lcol;

    float c[4][4][4];
#pragma unroll
    for (int a = 0; a < 4; ++a)
#pragma unroll
        for (int b = 0; b < 4; ++b)
#pragma unroll
            for (int r = 0; r < 4; ++r) c[a][b][r] = 0.f;

    float4 ra[4], rb[4];
#pragma unroll
    for (int r = 0; r < 4; ++r) {
        ra[r] = *(const float4*)(Ag + (size_t)r * 32 * HID);
        rb[r] = *(const float4*)(Bg + (size_t)r * 32 * HID);
    }
    {
        float* As = ps;
        float* Bs = ps + TBUF;
#pragma unroll
        for (int r = 0; r < 4; ++r) {
            int ro = (lrow + r * 32) * LDT + lcol;
            As[ro + 0] = __uint_as_float(tf32r(ra[r].x));
            As[ro + 1] = __uint_as_float(tf32r(ra[r].y));
            As[ro + 2] = __uint_as_float(tf32r(ra[r].z));
            As[ro + 3] = __uint_as_float(tf32r(ra[r].w));
            Bs[ro + 0] = __uint_as_float(tf32r(rb[r].x));
            Bs[ro + 1] = __uint_as_float(tf32r(rb[r].y));
            Bs[ro + 2] = __uint_as_float(tf32r(rb[r].z));
            Bs[ro + 3] = __uint_as_float(tf32r(rb[r].w));
        }
    }
    __syncthreads();

    for (int kt = 0; kt < HID / 32; ++kt) {
        bool more = kt + 1 < HID / 32;
        if (more) {
            const float* Ak = Ag + (kt + 1) * 32;
            const float* Bk = Bg + (kt + 1) * 32;
#pragma unroll
            for (int r = 0; r < 4; ++r) {
                ra[r] = *(const float4*)(Ak + (size_t)r * 32 * HID);
                rb[r] = *(const float4*)(Bk + (size_t)r * 32 * HID);
            }
        }
        const float* As = ps + (kt & 1) * 2 * TBUF;
        const float* Bs = As + TBUF;
#pragma unroll
        for (int kk = 0; kk < 4; ++kk) {
            unsigned af[4][4], bf[4][2];
#pragma unroll
            for (int fm = 0; fm < 4; ++fm) {
                int rb0 = (warp_m + fm * 16 + g) * LDT + kk * 8;
                af[fm][0] = __float_as_uint(As[rb0 + q]);
                af[fm][1] = __float_as_uint(As[rb0 + 8 * LDT + q]);
                af[fm][2] = __float_as_uint(As[rb0 + q + 4]);
                af[fm][3] = __float_as_uint(As[rb0 + 8 * LDT + q + 4]);
            }
#pragma unroll
            for (int fn = 0; fn < 4; ++fn) {
                int nb = (warp_n + fn * 8 + g) * LDT + kk * 8;
                bf[fn][0] = __float_as_uint(Bs[nb + q]);
                bf[fn][1] = __float_as_uint(Bs[nb + q + 4]);
            }
#pragma unroll
            for (int fm = 0; fm < 4; ++fm)
#pragma unroll
                for (int fn = 0; fn < 4; ++fn)
                    asm volatile(
                        "mma.sync.aligned.m16n8k8.row.col.f32.tf32.tf32.f32 "
                        "{%0,%1,%2,%3},{%4,%5,%6,%7},{%8,%9},{%0,%1,%2,%3};"
                        : "+f"(c[fm][fn][0]), "+f"(c[fm][fn][1]),
                          "+f"(c[fm][fn][2]), "+f"(c[fm][fn][3])
                        : "r"(af[fm][0]), "r"(af[fm][1]),
                          "r"(af[fm][2]), "r"(af[fm][3]),
                          "r"(bf[fn][0]), "r"(bf[fn][1]));
        }
        if (more) {
            float* Aw = ps + ((kt + 1) & 1) * 2 * TBUF;
            float* Bw = Aw + TBUF;
#pragma unroll
            for (int r = 0; r < 4; ++r) {
                int ro = (lrow + r * 32) * LDT + lcol;
                Aw[ro + 0] = __uint_as_float(tf32r(ra[r].x));
                Aw[ro + 1] = __uint_as_float(tf32r(ra[r].y));
                Aw[ro + 2] = __uint_as_float(tf32r(ra[r].z));
                Aw[ro + 3] = __uint_as_float(tf32r(ra[r].w));
                Bw[ro + 0] = __uint_as_float(tf32r(rb[r].x));
                Bw[ro + 1] = __uint_as_float(tf32r(rb[r].y));
                Bw[ro + 2] = __uint_as_float(tf32r(rb[r].z));
                Bw[ro + 3] = __uint_as_float(tf32r(rb[r].w));
            }
        }
        __syncthreads();
    }

#pragma unroll
    for (int fm = 0; fm < 4; ++fm) {
        int row0 = bm + warp_m + fm * 16 + g;
#pragma unroll
        for (int fn = 0; fn < 4; ++fn) {
            int col = bn + warp_n + fn * 8 + q * 2;
            float b0 = bias[col], b1 = bias[col + 1];
            float2 o0 = make_float2(c[fm][fn][0] + b0, c[fm][fn][1] + b1);
            float2 o1 = make_float2(c[fm][fn][2] + b0, c[fm][fn][3] + b1);
            *(float2*)(C + (size_t)row0 * VOCAB + col) = o0;
            *(float2*)(C + (size_t)(row0 + 8) * VOCAB + col) = o1;
        }
    }
}

// ---------------- persistent GRU recurrence, throttled sector-poll ring ----------
// 128 CTAs x 256 threads; warp w owns h index i = blk*8+w, Whh rows in registers.
// Each thread polls its own 4 CONTIGUOUS ring words (one 32B sector); the
// __syncthreads_and gates re-polls CTA-wide (throttles L2 poll traffic, which is
// what made the free-running spin of last round 3x slower).
__global__ void __launch_bounds__(RTHREADS, 1) recurrence_kernel(
    const float* __restrict__ enc_Whh, const float* __restrict__ enc_bhh,
    const float* __restrict__ dec_Whh, const float* __restrict__ dec_bhh)
{
    extern __shared__ float smem[];
    float* sh  = smem;                 // HID floats: current h
    float* sgx = smem + HID;           // SEQ*24 floats: this CTA's gx slice

    int tid = threadIdx.x;
    int warp = tid >> 5, lane = tid & 31;
    int base = blockIdx.x * 8;
    int i = base + warp;
    int s = 0;

    unsigned long long wr2[16], wz2[16], wn2[16];

    for (int phase = 0; phase < 2; ++phase) {
        const float* Whh = phase ? dec_Whh : enc_Whh;
        const float* bhh = phase ? dec_bhh : enc_bhh;
        const float* gxp = &g_GX[phase][0][0];

        {
            const float* w0 = Whh + (size_t)i * HID;
            const float* w1 = Whh + (size_t)(HID + i) * HID;
            const float* w2 = Whh + (size_t)(2 * HID + i) * HID;
#pragma unroll
            for (int k = 0; k < 8; ++k) {
                int cc = 4 * lane + 128 * k;
                float4 a = *(const float4*)(w0 + cc);
                wr2[2*k] = pk2(a.x, a.y); wr2[2*k+1] = pk2(a.z, a.w);
                float4 b = *(const float4*)(w1 + cc);
                wz2[2*k] = pk2(b.x, b.y); wz2[2*k+1] = pk2(b.z, b.w);
                float4 d = *(const float4*)(w2 + cc);
                wn2[2*k] = pk2(d.x, d.y); wn2[2*k+1] = pk2(d.z, d.w);
            }
        }
        float br = bhh[i], bz = bhh[HID + i], bnn = bhh[2 * HID + i];

        __syncthreads();               // all warps done with previous phase's sgx
        for (int idx = tid; idx < SEQ * 24; idx += RTHREADS) {
            int t = idx / 24;
            int rr = idx - t * 24;
            int w = rr / 3, gg = rr - 3 * w;
            sgx[idx] = gxp[(size_t)t * H3 + gg * HID + base + w];
        }
        __syncthreads();

        for (int t = 0; t < SEQ; ++t, ++s) {
            const unsigned long long* ring = g_ring[s % 3] + 4 * tid;
            unsigned exp = (unsigned)s;
            unsigned long long v0, v1, v2, v3;
            for (;;) {
                v0 = ldrx(ring);
                v1 = ldrx(ring + 1);
                v2 = ldrx(ring + 2);
                v3 = ldrx(ring + 3);
                bool ok = ((unsigned)(v0 >> 32) == exp) &&
                          ((unsigned)(v1 >> 32) == exp) &&
                          ((unsigned)(v2 >> 32) == exp) &&
                          ((unsigned)(v3 >> 32) == exp);
                if (__syncthreads_and(ok)) break;
            }
            int e = 4 * tid;
            sh[e + 0] = __uint_as_float((unsigned)v0);
            sh[e + 1] = __uint_as_float((unsigned)v1);
            sh[e + 2] = __uint_as_float((unsigned)v2);
            sh[e + 3] = __uint_as_float((unsigned)v3);
            __syncthreads();

            unsigned long long ar2 = 0ULL, az2 = 0ULL, an2 = 0ULL;
            const ulonglong2* shv = (const ulonglong2*)sh;
#pragma unroll
            for (int k = 0; k < 8; ++k) {
                ulonglong2 hv = shv[lane + 32 * k];
                ar2 = f2fma(wr2[2*k], hv.x, ar2); ar2 = f2fma(wr2[2*k+1], hv.y, ar2);
                az2 = f2fma(wz2[2*k], hv.x, az2); az2 = f2fma(wz2[2*k+1], hv.y, az2);
                an2 = f2fma(wn2[2*k], hv.x, an2); an2 = f2fma(wn2[2*k+1], hv.y, an2);
            }
            float2 arf = up2(ar2), azf = up2(az2), anf = up2(an2);
            float ar = arf.x + arf.y, az = azf.x + azf.y, an = anf.x + anf.y;
#pragma unroll
            for (int off = 16; off > 0; off >>= 1) {
                ar += __shfl_xor_sync(0xffffffffu, ar, off);
                az += __shfl_xor_sync(0xffffffffu, az, off);
                an += __shfl_xor_sync(0xffffffffu, an, off);
            }
            if (lane == 0) {
                const float* gx3 = &sgx[t * 24 + warp * 3];
                float r = 1.f / (1.f + expf(-(gx3[0] + ar + br)));
                float z = 1.f / (1.f + expf(-(gx3[1] + az + bz)));
                float n = tanhf(gx3[2] + r * (an + bnn));
                float hnew = (1.f - z) * n + z * sh[i];
                if (phase) g_dec_hs[t][i] = hnew;
                unsigned long long pub =
                    ((unsigned long long)(unsigned)(s + 1) << 32) |
                    (unsigned long long)__float_as_uint(hnew);
                strx(&g_ring[(s + 1) % 3][i], pub);
            }
            // next step's poll barrier orders sh reuse; no trailing barrier needed
        }
    }
}

// ---------------- launch ----------------
extern "C" void kernel_launch(void* const* d_in, const int* in_sizes, int n_in,
                              void* d_out, int out_size) {
    const int*   inputs  = (const int*)d_in[0];
    const int*   targets = (const int*)d_in[1];
    const float* emb     = (const float*)d_in[2];
    const float* enc_Wih = (const float*)d_in[3];
    const float* enc_Whh = (const float*)d_in[4];
    const float* enc_bih = (const float*)d_in[5];
    const float* enc_bhh = (const float*)d_in[6];
    const float* dec_Wih = (const float*)d_in[7];
    const float* dec_Whh = (const float*)d_in[8];
    const float* dec_bih = (const float*)d_in[9];
    const float* dec_bhh = (const float*)d_in[10];
    const float* proj_W  = (const float*)d_in[11];
    const float* proj_b  = (const float*)d_in[12];
    float* out = (float*)d_out;

    const int rec_smem  = (HID + SEQ * 24) * 4;          // 53,248 B
    const int proj_smem = 4 * TBUF * 4;                  // 73,728 B
    cudaFuncSetAttribute(recurrence_kernel,
                         cudaFuncAttributeMaxDynamicSharedMemorySize, rec_smem);
    cudaFuncSetAttribute(proj_mma_kernel,
                         cudaFuncAttributeMaxDynamicSharedMemorySize, proj_smem);

    init_kernel<<<1, 1024>>>();
    gather_kernel<<<2 * SEQ, 256>>>(inputs, targets, emb);

    dim3 g_gx(H3 / 128, SEQ / 128, 2);        // 24 x 4 x 2 = 192 blocks, one wave
    gemm_gx_kernel<<<g_gx, 256>>>(enc_Wih, dec_Wih, enc_bih, dec_bih);

    recurrence_kernel<<<RGRID, RTHREADS, rec_smem>>>(enc_Whh, enc_bhh,
                                                     dec_Whh, dec_bhh);

    dim3 g_proj(VOCAB / 128, SEQ / 128);      // 250 x 4
    proj_mma_kernel<<<g_proj, 256, proj_smem>>>(proj_W, proj_b, out);
}

// round 5
// speedup vs baseline: 2.1401x; 1.3491x over previous
#include <cuda_runtime.h>
#include <math.h>

#define HID    1024
#define H3     3072
#define SEQ    512
#define VOCAB  32000
#define RGRID  128
#define RTHREADS 256

// ---------------- device scratch (static: no allocations allowed) ----------------
__device__ float g_X[2][SEQ][HID];                 // embedded enc/dec inputs
__device__ float g_GX[2][SEQ][H3];                 // precomputed Wih@x + bih
__device__ float g_dec_hs[SEQ][HID];               // decoder hidden states
__device__ unsigned long long g_ring[3][HID];      // (tag<<32)|float bits, depth-3 ring

// ---------------- packed f32x2 helpers (FFMA2) -----------------------------------
__device__ __forceinline__ unsigned long long pk2(float x, float y) {
    unsigned long long r;
    asm("mov.b64 %0,{%1,%2};" : "=l"(r) : "f"(x), "f"(y));
    return r;
}
__device__ __forceinline__ unsigned long long f2fma(unsigned long long a,
                                                    unsigned long long b,
                                                    unsigned long long c) {
    unsigned long long d;
    asm("fma.rn.f32x2 %0,%1,%2,%3;" : "=l"(d) : "l"(a), "l"(b), "l"(c));
    return d;
}
__device__ __forceinline__ float2 up2(unsigned long long v) {
    float2 f;
    asm("mov.b64 {%0,%1},%2;" : "=f"(f.x), "=f"(f.y) : "l"(v));
    return f;
}
__device__ __forceinline__ unsigned long long ldrx(const unsigned long long* p) {
    unsigned long long v;
    asm volatile("ld.global.relaxed.gpu.b64 %0,[%1];" : "=l"(v) : "l"(p));
    return v;
}
__device__ __forceinline__ void strx(unsigned long long* p, unsigned long long v) {
    asm volatile("st.global.relaxed.gpu.b64 [%0],%1;" :: "l"(p), "l"(v) : "memory");
}
__device__ __forceinline__ unsigned tf32r(float x) {
    unsigned u;
    asm("cvt.rna.tf32.f32 %0,%1;" : "=r"(u) : "f"(x));
    return u;
}

// ---------------- init: must reset per replay (graph re-executes) ----------------
__global__ void init_kernel() {
    int tid = threadIdx.x;                       // 1024 threads
    g_ring[0][tid] = 0ULL;                       // tag 0, value 0.0f
    g_ring[1][tid] = 0xFFFFFFFF00000000ULL;      // sentinel tag
    g_ring[2][tid] = 0xFFFFFFFF00000000ULL;
}

// ---------------- embedding gather (encoder + teacher-forced decoder) ------------
__global__ void gather_kernel(const int* __restrict__ inputs,
                              const int* __restrict__ targets,
                              const float* __restrict__ emb) {
    int b = blockIdx.x;
    int phase = b >> 9;
    int t = b & (SEQ - 1);
    int tok = phase ? (t == 0 ? 0 : targets[t - 1]) : inputs[t];
    const float4* src = (const float4*)(emb + (size_t)tok * HID);
    float4* dst = (float4*)(&g_X[phase][t][0]);
    dst[threadIdx.x] = src[threadIdx.x];
}

// ---------------- fp32 NT GEMM (FFMA2) for the two gx precomputes ----------------
// grid.z = phase.  C = g_GX[z] = g_X[z] * Wih[z]^T + bih[z], N = 3072, K = 1024.
__global__ void __launch_bounds__(256, 2) gemm_gx_kernel(
    const float* __restrict__ B0, const float* __restrict__ B1,
    const float* __restrict__ bias0, const float* __restrict__ bias1)
{
    const int K = HID, N = H3;
    int mode = blockIdx.z;
    const float* A = &g_X[mode][0][0];
    const float* B = mode ? B1 : B0;
    const float* bias = mode ? bias1 : bias0;
    float* C = &g_GX[mode][0][0];

    __shared__ float As[2][16][132];
    __shared__ float Bs[2][16][132];

    int tid = threadIdx.x;
    int bm = blockIdx.y * 128;
    int bn = blockIdx.x * 128;
    int lrow = tid >> 2;
    int lcol = (tid & 3) << 2;
    int tx = tid & 15;
    int ty = tid >> 4;
    const float* Ab = A + (size_t)bm * K;
    const float* Bb = B + (size_t)bn * K;

    unsigned long long acc2[8][4];
#pragma unroll
    for (int i = 0; i < 8; ++i)
#pragma unroll
        for (int j = 0; j < 4; ++j) acc2[i][j] = 0ULL;

    float4 pa[2], pb[2];
#pragma unroll
    for (int r = 0; r < 2; ++r) {
        int row = lrow + r * 64;
        pa[r] = *(const float4*)(Ab + (size_t)row * K + lcol);
        pb[r] = *(const float4*)(Bb + (size_t)row * K + lcol);
    }
#pragma unroll
    for (int r = 0; r < 2; ++r) {
        int row = lrow + r * 64;
        As[0][lcol + 0][row] = pa[r].x; As[0][lcol + 1][row] = pa[r].y;
        As[0][lcol + 2][row] = pa[r].z; As[0][lcol + 3][row] = pa[r].w;
        Bs[0][lcol + 0][row] = pb[r].x; Bs[0][lcol + 1][row] = pb[r].y;
        Bs[0][lcol + 2][row] = pb[r].z; Bs[0][lcol + 3][row] = pb[r].w;
    }
    __syncthreads();

    int cur = 0;
    for (int k0 = 0; k0 < K; k0 += 16) {
        bool more = (k0 + 16) < K;
        if (more) {
#pragma unroll
            for (int r = 0; r < 2; ++r) {
                int row = lrow + r * 64;
                pa[r] = *(const float4*)(Ab + (size_t)row * K + k0 + 16 + lcol);
                pb[r] = *(const float4*)(Bb + (size_t)row * K + k0 + 16 + lcol);
            }
        }
#pragma unroll
        for (int kk = 0; kk < 16; ++kk) {
            float4 av0 = *(const float4*)&As[cur][kk][ty * 8];
            float4 av1 = *(const float4*)&As[cur][kk][ty * 8 + 4];
            ulonglong2 bv0 = *(const ulonglong2*)&Bs[cur][kk][tx * 8];
            ulonglong2 bv1 = *(const ulonglong2*)&Bs[cur][kk][tx * 8 + 4];
            unsigned long long a2[8];
            a2[0] = pk2(av0.x, av0.x); a2[1] = pk2(av0.y, av0.y);
            a2[2] = pk2(av0.z, av0.z); a2[3] = pk2(av0.w, av0.w);
            a2[4] = pk2(av1.x, av1.x); a2[5] = pk2(av1.y, av1.y);
            a2[6] = pk2(av1.z, av1.z); a2[7] = pk2(av1.w, av1.w);
#pragma unroll
            for (int i = 0; i < 8; ++i) {
                acc2[i][0] = f2fma(a2[i], bv0.x, acc2[i][0]);
                acc2[i][1] = f2fma(a2[i], bv0.y, acc2[i][1]);
                acc2[i][2] = f2fma(a2[i], bv1.x, acc2[i][2]);
                acc2[i][3] = f2fma(a2[i], bv1.y, acc2[i][3]);
            }
        }
        if (more) {
            int alt = cur ^ 1;
#pragma unroll
            for (int r = 0; r < 2; ++r) {
                int row = lrow + r * 64;
                As[alt][lcol + 0][row] = pa[r].x; As[alt][lcol + 1][row] = pa[r].y;
                As[alt][lcol + 2][row] = pa[r].z; As[alt][lcol + 3][row] = pa[r].w;
                Bs[alt][lcol + 0][row] = pb[r].x; Bs[alt][lcol + 1][row] = pb[r].y;
                Bs[alt][lcol + 2][row] = pb[r].z; Bs[alt][lcol + 3][row] = pb[r].w;
            }
        }
        __syncthreads();
        cur ^= 1;
    }

#pragma unroll
    for (int i = 0; i < 8; ++i) {
        int row = bm + ty * 8 + i;
        float2 c0 = up2(acc2[i][0]), c1 = up2(acc2[i][1]);
        float2 c2 = up2(acc2[i][2]), c3 = up2(acc2[i][3]);
        int col = bn + tx * 8;
        float4 o0, o1;
        o0.x = c0.x + bias[col + 0]; o0.y = c0.y + bias[col + 1];
        o0.z = c1.x + bias[col + 2]; o0.w = c1.y + bias[col + 3];
        o1.x = c2.x + bias[col + 4]; o1.y = c2.y + bias[col + 5];
        o1.z = c3.x + bias[col + 6]; o1.w = c3.y + bias[col + 7];
        *(float4*)(C + (size_t)row * N + col) = o0;
        *(float4*)(C + (size_t)row * N + col + 4) = o1;
    }
}

// ---------------- tf32 tensor-core projection: out = dec_hs * proj_W^T + b -------
// Block 128x128, K-tile 32, 8 warps (2m x 4n), warp tile 64x32 via m16n8k8 tf32.
#define LDT 36
#define TBUF (128 * LDT)            // floats per A (or B) buffer
__global__ void __launch_bounds__(256, 2) proj_mma_kernel(
    const float* __restrict__ W, const float* __restrict__ bias,
    float* __restrict__ C)
{
    extern __shared__ float ps[];   // [2][A:TBUF | B:TBUF]
    const float* A = &g_dec_hs[0][0];

    int tid = threadIdx.x;
    int lane = tid & 31, wid = tid >> 5;
    int bm = blockIdx.y * 128, bn = blockIdx.x * 128;
    int warp_m = (wid & 1) * 64, warp_n = (wid >> 1) * 32;
    int g = lane >> 2, q = lane & 3;

    int lrow = tid >> 3;            // 0..31
    int lcol = (tid & 7) * 4;       // k within tile
    const float* Ag = A + (size_t)(bm + lrow) * HID + lcol;
    const float* Bg = W + (size_t)(bn + lrow) * HID + lcol;

    float c[4][4][4];
#pragma unroll
    for (int a = 0; a < 4; ++a)
#pragma unroll
        for (int b = 0; b < 4; ++b)
#pragma unroll
            for (int r = 0; r < 4; ++r) c[a][b][r] = 0.f;

    float4 ra[4], rb[4];
#pragma unroll
    for (int r = 0; r < 4; ++r) {
        ra[r] = *(const float4*)(Ag + (size_t)r * 32 * HID);
        rb[r] = *(const float4*)(Bg + (size_t)r * 32 * HID);
    }
    {
        float* As = ps;
        float* Bs = ps + TBUF;
#pragma unroll
        for (int r = 0; r < 4; ++r) {
            int ro = (lrow + r * 32) * LDT + lcol;
            As[ro + 0] = __uint_as_float(tf32r(ra[r].x));
            As[ro + 1] = __uint_as_float(tf32r(ra[r].y));
            As[ro + 2] = __uint_as_float(tf32r(ra[r].z));
            As[ro + 3] = __uint_as_float(tf32r(ra[r].w));
            Bs[ro + 0] = __uint_as_float(tf32r(rb[r].x));
            Bs[ro + 1] = __uint_as_float(tf32r(rb[r].y));
            Bs[ro + 2] = __uint_as_float(tf32r(rb[r].z));
            Bs[ro + 3] = __uint_as_float(tf32r(rb[r].w));
        }
    }
    __syncthreads();

    for (int kt = 0; kt < HID / 32; ++kt) {
        bool more = kt + 1 < HID / 32;
        if (more) {
            const float* Ak = Ag + (kt + 1) * 32;
            const float* Bk = Bg + (kt + 1) * 32;
#pragma unroll
            for (int r = 0; r < 4; ++r) {
                ra[r] = *(const float4*)(Ak + (size_t)r * 32 * HID);
                rb[r] = *(const float4*)(Bk + (size_t)r * 32 * HID);
            }
        }
        const float* As = ps + (kt & 1) * 2 * TBUF;
        const float* Bs = As + TBUF;
#pragma unroll
        for (int kk = 0; kk < 4; ++kk) {
            unsigned af[4][4], bf[4][2];
#pragma unroll
            for (int fm = 0; fm < 4; ++fm) {
                int rb0 = (warp_m + fm * 16 + g) * LDT + kk * 8;
                af[fm][0] = __float_as_uint(As[rb0 + q]);
                af[fm][1] = __float_as_uint(As[rb0 + 8 * LDT + q]);
                af[fm][2] = __float_as_uint(As[rb0 + q + 4]);
                af[fm][3] = __float_as_uint(As[rb0 + 8 * LDT + q + 4]);
            }
#pragma unroll
            for (int fn = 0; fn < 4; ++fn) {
                int nb = (warp_n + fn * 8 + g) * LDT + kk * 8;
                bf[fn][0] = __float_as_uint(Bs[nb + q]);
                bf[fn][1] = __float_as_uint(Bs[nb + q + 4]);
            }
#pragma unroll
            for (int fm = 0; fm < 4; ++fm)
#pragma unroll
                for (int fn = 0; fn < 4; ++fn)
                    asm volatile(
                        "mma.sync.aligned.m16n8k8.row.col.f32.tf32.tf32.f32 "
                        "{%0,%1,%2,%3},{%4,%5,%6,%7},{%8,%9},{%0,%1,%2,%3};"
                        : "+f"(c[fm][fn][0]), "+f"(c[fm][fn][1]),
                          "+f"(c[fm][fn][2]), "+f"(c[fm][fn][3])
                        : "r"(af[fm][0]), "r"(af[fm][1]),
                          "r"(af[fm][2]), "r"(af[fm][3]),
                          "r"(bf[fn][0]), "r"(bf[fn][1]));
        }
        if (more) {
            float* Aw = ps + ((kt + 1) & 1) * 2 * TBUF;
            float* Bw = Aw + TBUF;
#pragma unroll
            for (int r = 0; r < 4; ++r) {
                int ro = (lrow + r * 32) * LDT + lcol;
                Aw[ro + 0] = __uint_as_float(tf32r(ra[r].x));
                Aw[ro + 1] = __uint_as_float(tf32r(ra[r].y));
                Aw[ro + 2] = __uint_as_float(tf32r(ra[r].z));
                Aw[ro + 3] = __uint_as_float(tf32r(ra[r].w));
                Bw[ro + 0] = __uint_as_float(tf32r(rb[r].x));
                Bw[ro + 1] = __uint_as_float(tf32r(rb[r].y));
                Bw[ro + 2] = __uint_as_float(tf32r(rb[r].z));
                Bw[ro + 3] = __uint_as_float(tf32r(rb[r].w));
            }
        }
        __syncthreads();
    }

#pragma unroll
    for (int fm = 0; fm < 4; ++fm) {
        int row0 = bm + warp_m + fm * 16 + g;
#pragma unroll
        for (int fn = 0; fn < 4; ++fn) {
            int col = bn + warp_n + fn * 8 + q * 2;
            float b0 = bias[col], b1 = bias[col + 1];
            float2 o0 = make_float2(c[fm][fn][0] + b0, c[fm][fn][1] + b1);
            float2 o1 = make_float2(c[fm][fn][2] + b0, c[fm][fn][3] + b1);
            *(float2*)(C + (size_t)row0 * VOCAB + col) = o0;
            *(float2*)(C + (size_t)(row0 + 8) * VOCAB + col) = o1;
        }
    }
}

// ---------------- persistent GRU recurrence, throttled WARP-COALESCED poll -------
// 128 CTAs x 256 threads; warp w owns h index i = blk*8+w, Whh rows in registers.
// Poll addressing is tid-strided (ring[tid], [tid+256], [tid+512], [tid+768]):
// each warp-wide 64-bit load covers 32 consecutive words = 8 contiguous 32B
// sectors. (Round 4's per-thread-contiguous variant touched 32 sectors per load
// -> 4x L2 wavefront amplification on the serial critical path; -800us here.)
__global__ void __launch_bounds__(RTHREADS, 1) recurrence_kernel(
    const float* __restrict__ enc_Whh, const float* __restrict__ enc_bhh,
    const float* __restrict__ dec_Whh, const float* __restrict__ dec_bhh)
{
    extern __shared__ float smem[];
    float* sh  = smem;                 // HID floats: current h
    float* sgx = smem + HID;           // SEQ*24 floats: this CTA's gx slice

    int tid = threadIdx.x;
    int warp = tid >> 5, lane = tid & 31;
    int base = blockIdx.x * 8;
    int i = base + warp;
    int s = 0;

    unsigned long long wr2[16], wz2[16], wn2[16];

    for (int phase = 0; phase < 2; ++phase) {
        const float* Whh = phase ? dec_Whh : enc_Whh;
        const float* bhh = phase ? dec_bhh : enc_bhh;
        const float* gxp = &g_GX[phase][0][0];

        {
            const float* w0 = Whh + (size_t)i * HID;
            const float* w1 = Whh + (size_t)(HID + i) * HID;
            const float* w2 = Whh + (size_t)(2 * HID + i) * HID;
#pragma unroll
            for (int k = 0; k < 8; ++k) {
                int cc = 4 * lane + 128 * k;
                float4 a = *(const float4*)(w0 + cc);
                wr2[2*k] = pk2(a.x, a.y); wr2[2*k+1] = pk2(a.z, a.w);
                float4 b = *(const float4*)(w1 + cc);
                wz2[2*k] = pk2(b.x, b.y); wz2[2*k+1] = pk2(b.z, b.w);
                float4 d = *(const float4*)(w2 + cc);
                wn2[2*k] = pk2(d.x, d.y); wn2[2*k+1] = pk2(d.z, d.w);
            }
        }
        float br = bhh[i], bz = bhh[HID + i], bnn = bhh[2 * HID + i];

        __syncthreads();               // all warps done with previous phase's sgx
        for (int idx = tid; idx < SEQ * 24; idx += RTHREADS) {
            int t = idx / 24;
            int rr = idx - t * 24;
            int w = rr / 3, gg = rr - 3 * w;
            sgx[idx] = gxp[(size_t)t * H3 + gg * HID + base + w];
        }
        __syncthreads();

        for (int t = 0; t < SEQ; ++t, ++s) {
            const unsigned long long* ring = g_ring[s % 3];
            unsigned exp = (unsigned)s;
            unsigned long long v0, v1, v2, v3;
            for (;;) {
                v0 = ldrx(ring + tid);
                v1 = ldrx(ring + tid + 256);
                v2 = ldrx(ring + tid + 512);
                v3 = ldrx(ring + tid + 768);
                bool ok = ((unsigned)(v0 >> 32) == exp) &&
                          ((unsigned)(v1 >> 32) == exp) &&
                          ((unsigned)(v2 >> 32) == exp) &&
                          ((unsigned)(v3 >> 32) == exp);
                if (__syncthreads_and(ok)) break;
            }
            sh[tid      ] = __uint_as_float((unsigned)v0);
            sh[tid + 256] = __uint_as_float((unsigned)v1);
            sh[tid + 512] = __uint_as_float((unsigned)v2);
            sh[tid + 768] = __uint_as_float((unsigned)v3);
            __syncthreads();

            unsigned long long ar2 = 0ULL, az2 = 0ULL, an2 = 0ULL;
            const ulonglong2* shv = (const ulonglong2*)sh;
#pragma unroll
            for (int k = 0; k < 8; ++k) {
                ulonglong2 hv = shv[lane + 32 * k];
                ar2 = f2fma(wr2[2*k], hv.x, ar2); ar2 = f2fma(wr2[2*k+1], hv.y, ar2);
                az2 = f2fma(wz2[2*k], hv.x, az2); az2 = f2fma(wz2[2*k+1], hv.y, az2);
                an2 = f2fma(wn2[2*k], hv.x, an2); an2 = f2fma(wn2[2*k+1], hv.y, an2);
            }
            float2 arf = up2(ar2), azf = up2(az2), anf = up2(an2);
            float ar = arf.x + arf.y, az = azf.x + azf.y, an = anf.x + anf.y;
#pragma unroll
            for (int off = 16; off > 0; off >>= 1) {
                ar += __shfl_xor_sync(0xffffffffu, ar, off);
                az += __shfl_xor_sync(0xffffffffu, az, off);
                an += __shfl_xor_sync(0xffffffffu, an, off);
            }
            if (lane == 0) {
                const float* gx3 = &sgx[t * 24 + warp * 3];
                float r = 1.f / (1.f + expf(-(gx3[0] + ar + br)));
                float z = 1.f / (1.f + expf(-(gx3[1] + az + bz)));
                float n = tanhf(gx3[2] + r * (an + bnn));
                float hnew = (1.f - z) * n + z * sh[i];
                if (phase) g_dec_hs[t][i] = hnew;
                unsigned long long pub =
                    ((unsigned long long)(unsigned)(s + 1) << 32) |
                    (unsigned long long)__float_as_uint(hnew);
                strx(&g_ring[(s + 1) % 3][i], pub);
            }
            // next step's poll barrier orders sh reuse; no trailing barrier needed
        }
    }
}

// ---------------- launch ----------------
extern "C" void kernel_launch(void* const* d_in, const int* in_sizes, int n_in,
                              void* d_out, int out_size) {
    const int*   inputs  = (const int*)d_in[0];
    const int*   targets = (const int*)d_in[1];
    const float* emb     = (const float*)d_in[2];
    const float* enc_Wih = (const float*)d_in[3];
    const float* enc_Whh = (const float*)d_in[4];
    const float* enc_bih = (const float*)d_in[5];
    const float* enc_bhh = (const float*)d_in[6];
    const float* dec_Wih = (const float*)d_in[7];
    const float* dec_Whh = (const float*)d_in[8];
    const float* dec_bih = (const float*)d_in[9];
    const float* dec_bhh = (const float*)d_in[10];
    const float* proj_W  = (const float*)d_in[11];
    const float* proj_b  = (const float*)d_in[12];
    float* out = (float*)d_out;

    const int rec_smem  = (HID + SEQ * 24) * 4;          // 53,248 B
    const int proj_smem = 4 * TBUF * 4;                  // 73,728 B
    cudaFuncSetAttribute(recurrence_kernel,
                         cudaFuncAttributeMaxDynamicSharedMemorySize, rec_smem);
    cudaFuncSetAttribute(proj_mma_kernel,
                         cudaFuncAttributeMaxDynamicSharedMemorySize, proj_smem);

    init_kernel<<<1, 1024>>>();
    gather_kernel<<<2 * SEQ, 256>>>(inputs, targets, emb);

    dim3 g_gx(H3 / 128, SEQ / 128, 2);        // 24 x 4 x 2 = 192 blocks, one wave
    gemm_gx_kernel<<<g_gx, 256>>>(enc_Wih, dec_Wih, enc_bih, dec_bih);

    recurrence_kernel<<<RGRID, RTHREADS, rec_smem>>>(enc_Whh, enc_bhh,
                                                     dec_Whh, dec_bhh);

    dim3 g_proj(VOCAB / 128, SEQ / 128);      // 250 x 4
    proj_mma_kernel<<<g_proj, 256, proj_smem>>>(proj_W, proj_b, out);
}